// round 1
// baseline (speedup 1.0000x reference)
#include <cuda_runtime.h>
#include <math.h>

#define T_LEN   32768
#define B_SEG   8
#define H_HEADS 8
#define D_DIM   128
#define C_COLS  1024            // H*D
#define C4      256             // float4 columns

// ---------------- scratch (device globals; zero-initialized at load) ----------
__device__ float g_accum[B_SEG * C_COLS];   // per-(segment, col) sums; MUST be 0 at entry
__device__ float g_h1[B_SEG * 1024];        // after layer1 + silu
__device__ float g_h2[B_SEG * 256];         // after layer2 (no act)
__device__ float g_h3[B_SEG * 512];         // after layer3 + silu

__device__ __forceinline__ float silu(float v) {
    return v / (1.0f + expf(-v));
}

// ---------------- K1: segment sum -------------------------------------------
// grid 512, block 256. Block b handles rows [b*64, b*64+64). Thread owns float4 col tid.
__global__ void __launch_bounds__(256) reduce_kernel(
    const float4* __restrict__ x4, const int* __restrict__ cu)
{
    const int tid = threadIdx.x;
    const int t0  = blockIdx.x * 64;

    __shared__ int scu[B_SEG + 1];
    if (tid <= B_SEG) scu[tid] = cu[tid];
    __syncthreads();

    const int t1 = t0 + 63;
    int s0 = 0; while (s0 < B_SEG - 1 && t0 >= scu[s0 + 1]) s0++;
    int s1 = 0; while (s1 < B_SEG - 1 && t1 >= scu[s1 + 1]) s1++;

    const float4* xp = x4 + (size_t)t0 * C4 + tid;

    if (s0 == s1) {
        // fast path: whole block inside one segment
        float4 a = make_float4(0.f, 0.f, 0.f, 0.f);
        #pragma unroll 8
        for (int r = 0; r < 64; r++) {
            float4 v = xp[r * C4];
            a.x += v.x; a.y += v.y; a.z += v.z; a.w += v.w;
        }
        float* dst = g_accum + s0 * C_COLS + tid * 4;
        atomicAdd(dst + 0, a.x);
        atomicAdd(dst + 1, a.y);
        atomicAdd(dst + 2, a.z);
        atomicAdd(dst + 3, a.w);
    } else {
        // slow path: segment boundary inside this block (<=7 blocks total)
        float4 a = make_float4(0.f, 0.f, 0.f, 0.f);
        int seg = s0;
        int nxt = (seg < B_SEG - 1) ? scu[seg + 1] : 0x7fffffff;
        for (int r = 0; r < 64; r++) {
            int t = t0 + r;
            if (t >= nxt) {
                float* dst = g_accum + seg * C_COLS + tid * 4;
                atomicAdd(dst + 0, a.x);
                atomicAdd(dst + 1, a.y);
                atomicAdd(dst + 2, a.z);
                atomicAdd(dst + 3, a.w);
                a = make_float4(0.f, 0.f, 0.f, 0.f);
                while (seg < B_SEG - 1 && t >= scu[seg + 1]) seg++;
                nxt = (seg < B_SEG - 1) ? scu[seg + 1] : 0x7fffffff;
            }
            float4 v = xp[r * C4];
            a.x += v.x; a.y += v.y; a.z += v.z; a.w += v.w;
        }
        float* dst = g_accum + seg * C_COLS + tid * 4;
        atomicAdd(dst + 0, a.x);
        atomicAdd(dst + 1, a.y);
        atomicAdd(dst + 2, a.z);
        atomicAdd(dst + 3, a.w);
    }
}

// ---------------- K2: pooled mean + layer1 (+silu) ---------------------------
// grid 8, block 128. Block g computes outputs j = g*128 + tid (j in [0,1024)).
__global__ void __launch_bounds__(128) layer1_kernel(
    const int* __restrict__ cu,
    const float* __restrict__ w1, const float* __restrict__ b1)
{
    const int tid = threadIdx.x;
    // pooled stored transposed: pooled[k*8 + b] for float4 broadcast loads
    __shared__ float pooled[D_DIM * B_SEG];     // 4 KB
    __shared__ float inv_s[B_SEG];

    if (tid < B_SEG) {
        int cnt = cu[tid + 1] - cu[tid];
        if (cnt < 1) cnt = 1;
        inv_s[tid] = 1.0f / ((float)cnt * (float)H_HEADS);
    }
    __syncthreads();

    for (int i = tid; i < D_DIM * B_SEG; i += 128) {
        int k = i >> 3;          // d index
        int b = i & 7;
        float s = 0.f;
        #pragma unroll
        for (int h = 0; h < H_HEADS; h++)
            s += g_accum[b * C_COLS + h * D_DIM + k];
        pooled[k * 8 + b] = s * inv_s[b];
    }
    __syncthreads();

    const int j = blockIdx.x * 128 + tid;
    float acc[8];
    #pragma unroll
    for (int b = 0; b < 8; b++) acc[b] = b1[j];

    #pragma unroll 4
    for (int k = 0; k < D_DIM; k++) {
        float w = w1[k * 1024 + j];
        float4 p0 = *(const float4*)&pooled[k * 8];
        float4 p1 = *(const float4*)&pooled[k * 8 + 4];
        acc[0] += p0.x * w; acc[1] += p0.y * w;
        acc[2] += p0.z * w; acc[3] += p0.w * w;
        acc[4] += p1.x * w; acc[5] += p1.y * w;
        acc[6] += p1.z * w; acc[7] += p1.w * w;
    }
    #pragma unroll
    for (int b = 0; b < 8; b++)
        g_h1[b * 1024 + j] = silu(acc[b]);
}

// ---------------- K3/K4: generic mid layer Y[8][N] = act(X[8][K] @ W + bias) --
// block 256 = 16 outputs x 16 k-slices. grid = N/16.
template <int K, int N, bool ACT>
__global__ void __launch_bounds__(256) mid_layer_kernel(
    const float* __restrict__ X, const float* __restrict__ W,
    const float* __restrict__ Bv, float* __restrict__ Y)
{
    const int tid = threadIdx.x;
    __shared__ float xs[K * 8];          // transposed: xs[k*8 + b]
    __shared__ float red[16 * 16 * 8];   // [slice][jj][b]

    for (int i = tid; i < K * 8; i += 256) {
        int b = i / K;
        int k = i - b * K;
        xs[k * 8 + b] = X[b * K + k];
    }
    __syncthreads();

    const int jj    = tid >> 4;
    const int slice = tid & 15;
    const int j     = blockIdx.x * 16 + jj;
    constexpr int KC = K / 16;

    float acc[8];
    #pragma unroll
    for (int b = 0; b < 8; b++) acc[b] = 0.f;

    const int k0 = slice * KC;
    #pragma unroll 4
    for (int k = k0; k < k0 + KC; k++) {
        float w = W[k * N + j];
        float4 p0 = *(const float4*)&xs[k * 8];
        float4 p1 = *(const float4*)&xs[k * 8 + 4];
        acc[0] += p0.x * w; acc[1] += p0.y * w;
        acc[2] += p0.z * w; acc[3] += p0.w * w;
        acc[4] += p1.x * w; acc[5] += p1.y * w;
        acc[6] += p1.z * w; acc[7] += p1.w * w;
    }

    float* r = &red[(slice * 16 + jj) * 8];
    #pragma unroll
    for (int b = 0; b < 8; b++) r[b] = acc[b];
    __syncthreads();

    if (tid < 128) {
        int ojj = tid >> 3;
        int b   = tid & 7;
        float s = 0.f;
        #pragma unroll
        for (int sl = 0; sl < 16; sl++)
            s += red[(sl * 16 + ojj) * 8 + b];
        int oj = blockIdx.x * 16 + ojj;
        s += Bv[oj];
        if (ACT) s = silu(s);
        Y[b * N + oj] = s;
    }
}

// ---------------- K5: layer4(+silu) + layer5 + argmax + output + accum reset --
// grid 8 (one block per batch row), block 256.
__global__ void __launch_bounds__(256) final_kernel(
    const float* __restrict__ w4, const float* __restrict__ b4,
    const float* __restrict__ w5, const float* __restrict__ b5,
    float* __restrict__ out)
{
    const int tid = threadIdx.x;
    const int b   = blockIdx.x;

    __shared__ float x3[512];
    __shared__ float red[256];
    __shared__ float h4s[128];
    __shared__ float l0[128];
    __shared__ float l1[128];

    #pragma unroll
    for (int i = tid; i < 512; i += 256)
        x3[i] = g_h3[b * 512 + i];
    __syncthreads();

    const int jj = tid & 127;
    const int sl = tid >> 7;
    float acc = 0.f;
    const int k0 = sl * 256;
    #pragma unroll 4
    for (int k = k0; k < k0 + 256; k++)
        acc += x3[k] * w4[k * 128 + jj];
    red[sl * 128 + jj] = acc;
    __syncthreads();

    if (tid < 128) {
        float v = red[tid] + red[128 + tid] + b4[tid];
        v = silu(v);
        h4s[tid] = v;
    }
    __syncthreads();

    if (tid < 128) {
        float v = h4s[tid];
        l0[tid] = v * w5[tid * 2 + 0];
        l1[tid] = v * w5[tid * 2 + 1];
    }
    __syncthreads();
    #pragma unroll
    for (int stride = 64; stride > 0; stride >>= 1) {
        if (tid < stride) {
            l0[tid] += l0[tid + stride];
            l1[tid] += l1[tid + stride];
        }
        __syncthreads();
    }

    if (tid == 0) {
        float lg0 = l0[0] + b5[0];
        float lg1 = l1[0] + b5[1];
        float z = (lg1 > lg0) ? 1.0f : 0.0f;   // argmax; ties -> class 0
        #pragma unroll
        for (int h = 0; h < H_HEADS; h++)
            out[b * H_HEADS + h] = z;
    }

    // reset accumulator for next graph replay (keeps entry invariant accum==0)
    for (int i = tid; i < C_COLS; i += 256)
        g_accum[b * C_COLS + i] = 0.f;
}

// ---------------- launch ------------------------------------------------------
extern "C" void kernel_launch(void* const* d_in, const int* in_sizes, int n_in,
                              void* d_out, int out_size)
{
    const float* x  = (const float*)d_in[0];
    const int*   cu = (const int*)  d_in[1];
    const float* w1 = (const float*)d_in[2];
    const float* b1 = (const float*)d_in[3];
    const float* w2 = (const float*)d_in[4];
    const float* b2 = (const float*)d_in[5];
    const float* w3 = (const float*)d_in[6];
    const float* b3 = (const float*)d_in[7];
    const float* w4 = (const float*)d_in[8];
    const float* b4 = (const float*)d_in[9];
    const float* w5 = (const float*)d_in[10];
    const float* b5 = (const float*)d_in[11];
    float* out = (float*)d_out;

    reduce_kernel<<<512, 256>>>((const float4*)x, cu);
    layer1_kernel<<<8, 128>>>(cu, w1, b1);

    float* h1; cudaGetSymbolAddress((void**)&h1, g_h1);
    float* h2; cudaGetSymbolAddress((void**)&h2, g_h2);
    float* h3; cudaGetSymbolAddress((void**)&h3, g_h3);

    mid_layer_kernel<1024, 256, false><<<16, 256>>>(h1, w2, b2, h2);
    mid_layer_kernel< 256, 512, true ><<<32, 256>>>(h2, w3, b3, h3);

    final_kernel<<<8, 256>>>(w4, b4, w5, b5, out);
}